// round 1
// baseline (speedup 1.0000x reference)
#include <cuda_runtime.h>
#include <cstdint>

#define IMW   1024
#define IMH   1024
#define HW    (1024*1024)
#define BATCH 16
#define NPIX  (16u*1024u*1024u)
#define TR    64           // output rows per edge block
#define WPR   32           // 32-bit words per row (1024/32)

// ---------------- device scratch (static; no allocations) ----------------
__device__ double        g_acc[4];                     // A0, B0, A1, B1
__device__ unsigned int  g_E;                          // edge pixel count
__device__ unsigned int  g_ebits[BATCH * IMH * WPR];   // packed edge mask (2 MB)
__device__ unsigned int  g_tbits[BATCH * IMH * WPR];   // packed target   (2 MB)

// ---------------- kernel 0: zero accumulators (graph replays) -------------
__global__ void init_kernel() {
    if (threadIdx.x < 4) g_acc[threadIdx.x] = 0.0;
    if (threadIdx.x == 0) g_E = 0u;
}

// ---------------- kernel 1: bitwise 11x11 edge detector -------------------
// edge(t)=0  iff  (t==1 AND all 11x11 window ==1, zero-padded)
//             or  (t==0 AND all 11x11 window ==0, zero-padded)
// => edge = (t & ~AND11x11) | (~t & OR11x11)   on packed bits.
__global__ __launch_bounds__(256) void edge_kernel(const int* __restrict__ target) {
    __shared__ unsigned sp[TR + 10][WPR];   // packed target rows (with halo)
    __shared__ unsigned sa[TR + 10][WPR];   // horizontal AND-11
    __shared__ unsigned so[TR + 10][WPR];   // horizontal OR-11

    const int b    = blockIdx.y;
    const int r0   = blockIdx.x * TR;
    const int tid  = threadIdx.x;
    const int lane = tid & 31;
    const int warp = tid >> 5;
    const int* tb  = target + (size_t)b * HW;

    // pack target -> bits via ballot (one word per warp-iteration)
    for (int j = warp; j < (TR + 10) * WPR; j += 8) {
        const int lr = j >> 5, wc = j & 31;
        const int gr = r0 - 5 + lr;
        unsigned w = 0u;
        if (gr >= 0 && gr < IMH)
            w = __ballot_sync(0xffffffffu, tb[gr * IMW + wc * 32 + lane] != 0);
        if (lane == 0) sp[lr][wc] = w;
    }
    __syncthreads();

    // horizontal 11-tap AND/OR with funnel shifts across word boundaries
    for (int j = tid; j < (TR + 10) * WPR; j += 256) {
        const int lr = j >> 5, wc = j & 31;
        const unsigned c = sp[lr][wc];
        const unsigned l = (wc > 0)        ? sp[lr][wc - 1] : 0u;
        const unsigned r = (wc < WPR - 1)  ? sp[lr][wc + 1] : 0u;
        unsigned a = c, o = c;
        #pragma unroll
        for (int k = 1; k <= 5; k++) {
            const unsigned sr = __funnelshift_r(c, r, k);  // bit i <- col i+k
            const unsigned sl = __funnelshift_l(l, c, k);  // bit i <- col i-k
            a &= (sr & sl);
            o |= (sr | sl);
        }
        sa[lr][wc] = a;
        so[lr][wc] = o;
    }
    __syncthreads();

    // vertical 11-row combine, emit packed edge + target, count edges
    unsigned ecnt = 0u;
    for (int j = tid; j < TR * WPR; j += 256) {
        const int orow = j >> 5, wc = j & 31;
        const int lr = orow + 5;
        unsigned vA = 0xffffffffu, vO = 0u;
        #pragma unroll
        for (int k = -5; k <= 5; k++) {
            vA &= sa[lr + k][wc];
            vO |= so[lr + k][wc];
        }
        const unsigned t = sp[lr][wc];
        const unsigned e = (t & ~vA) | (~t & vO);
        const int gi = (b * IMH + r0 + orow) * WPR + wc;
        g_ebits[gi] = e;
        g_tbits[gi] = t;
        ecnt += __popc(e);
    }

    // reduce edge count
    #pragma unroll
    for (int off = 16; off > 0; off >>= 1)
        ecnt += __shfl_down_sync(0xffffffffu, ecnt, off);
    __shared__ unsigned wsum[8];
    if (lane == 0) wsum[warp] = ecnt;
    __syncthreads();
    if (tid == 0) {
        unsigned s = 0u;
        #pragma unroll
        for (int i = 0; i < 8; i++) s += wsum[i];
        atomicAdd(&g_E, s);
    }
}

// ---------------- kernel 2: fused log-softmax + masked reductions ---------
__device__ __forceinline__ void proc_px(float x0, float x1, unsigned t, unsigned e,
                                        float& A, float& B) {
    const float m   = fmaxf(x0, x1);
    const float l1p = __logf(1.0f + __expf(-fabsf(x0 - x1)));
    const float lse = m + l1p;
    const float lp0 = x0 - lse;
    const float lp1 = x1 - lse;
    const float lpt = t ? lp1 : lp0;
    A += lpt;
    if (e) B += (lp0 + lp1) - 1.5f * lpt;
}

__global__ __launch_bounds__(256) void main_kernel(const float* __restrict__ s0,
                                                   const float* __restrict__ s1) {
    float A0 = 0.f, B0 = 0.f, A1 = 0.f, B1 = 0.f;
    const unsigned nch    = NPIX / 4u;                      // 4-pixel chunks
    const unsigned stride = gridDim.x * blockDim.x;
    for (unsigned c = blockIdx.x * blockDim.x + threadIdx.x; c < nch; c += stride) {
        const unsigned p   = c * 4u;
        const unsigned b   = p >> 20;          // p / HW
        const unsigned pix = p & (HW - 1u);
        const size_t base  = (size_t)b * 2u * HW + pix;

        const float4 x0 = *(const float4*)(s0 + base);
        const float4 y0 = *(const float4*)(s0 + base + HW);
        const float4 x1 = *(const float4*)(s1 + base);
        const float4 y1 = *(const float4*)(s1 + base + HW);

        const unsigned sh = p & 31u;
        const unsigned ew = g_ebits[p >> 5] >> sh;
        const unsigned tw = g_tbits[p >> 5] >> sh;

        proc_px(x0.x, y0.x,  tw       & 1u,  ew       & 1u, A0, B0);
        proc_px(x0.y, y0.y, (tw >> 1) & 1u, (ew >> 1) & 1u, A0, B0);
        proc_px(x0.z, y0.z, (tw >> 2) & 1u, (ew >> 2) & 1u, A0, B0);
        proc_px(x0.w, y0.w, (tw >> 3) & 1u, (ew >> 3) & 1u, A0, B0);

        proc_px(x1.x, y1.x,  tw       & 1u,  ew       & 1u, A1, B1);
        proc_px(x1.y, y1.y, (tw >> 1) & 1u, (ew >> 1) & 1u, A1, B1);
        proc_px(x1.z, y1.z, (tw >> 2) & 1u, (ew >> 2) & 1u, A1, B1);
        proc_px(x1.w, y1.w, (tw >> 3) & 1u, (ew >> 3) & 1u, A1, B1);
    }

    // block reduction: warp shuffle (float), cross-warp in shared, double atomics
    #pragma unroll
    for (int off = 16; off > 0; off >>= 1) {
        A0 += __shfl_down_sync(0xffffffffu, A0, off);
        B0 += __shfl_down_sync(0xffffffffu, B0, off);
        A1 += __shfl_down_sync(0xffffffffu, A1, off);
        B1 += __shfl_down_sync(0xffffffffu, B1, off);
    }
    __shared__ float red[8][4];
    const int lane = threadIdx.x & 31, warp = threadIdx.x >> 5;
    if (lane == 0) { red[warp][0] = A0; red[warp][1] = B0; red[warp][2] = A1; red[warp][3] = B1; }
    __syncthreads();
    if (threadIdx.x == 0) {
        double a0 = 0, b0 = 0, a1 = 0, b1 = 0;
        #pragma unroll
        for (int i = 0; i < 8; i++) {
            a0 += (double)red[i][0]; b0 += (double)red[i][1];
            a1 += (double)red[i][2]; b1 += (double)red[i][3];
        }
        atomicAdd(&g_acc[0], a0);
        atomicAdd(&g_acc[1], b0);
        atomicAdd(&g_acc[2], a1);
        atomicAdd(&g_acc[3], b1);
    }
}

// ---------------- kernel 3: finalize scalar --------------------------------
__global__ void fin_kernel(float* __restrict__ out) {
    const double N = (double)NPIX;
    double alpha = (double)g_E / N;
    if (alpha > 0.2) alpha = 0.2;
    const double l0 = -(g_acc[0] + alpha * g_acc[1]) / N;
    const double l1 = -(g_acc[2] + alpha * g_acc[3]) / N;
    out[0] = (float)(l0 + 0.5 * l1);
}

// ---------------- launch ---------------------------------------------------
extern "C" void kernel_launch(void* const* d_in, const int* in_sizes, int n_in,
                              void* d_out, int out_size) {
    const float* s0  = (const float*)d_in[0];
    const float* s1  = (const float*)d_in[1];
    const int*   tgt = (const int*)d_in[2];

    init_kernel<<<1, 32>>>();
    edge_kernel<<<dim3(IMH / TR, BATCH), 256>>>(tgt);
    main_kernel<<<4096, 256>>>(s0, s1);
    fin_kernel<<<1, 1>>>((float*)d_out);
}

// round 2
// speedup vs baseline: 2.2399x; 2.2399x over previous
#include <cuda_runtime.h>
#include <cstdint>

#define IMW   1024
#define IMH   1024
#define HW    (1024*1024)
#define BATCH 16
#define NPIX  (16u*1024u*1024u)
#define TR    64           // output rows per edge block
#define WPR   32           // 32-bit words per row (1024/32)

// ---------------- device scratch (static; no allocations) ----------------
__device__ double        g_acc[4];                     // A0, B0, A1, B1
__device__ unsigned int  g_E;                          // edge pixel count
__device__ unsigned int  g_ebits[BATCH * IMH * WPR];   // packed edge mask (2 MB)
__device__ unsigned int  g_tbits[BATCH * IMH * WPR];   // packed target   (2 MB)

// ---------------- kernel 0: zero accumulators (graph replays) -------------
__global__ void init_kernel() {
    if (threadIdx.x < 4) g_acc[threadIdx.x] = 0.0;
    if (threadIdx.x == 0) g_E = 0u;
}

// ---------------- kernel 1: bitwise 11x11 edge detector -------------------
// edge(t)=0  iff  (t==1 AND all 11x11 window ==1, zero-padded)
//             or  (t==0 AND all 11x11 window ==0, zero-padded)
// => edge = (t & ~AND11x11) | (~t & OR11x11)   on packed bits.
__global__ __launch_bounds__(256) void edge_kernel(const int* __restrict__ target) {
    __shared__ unsigned sp[TR + 10][WPR];   // packed target rows (with halo)
    __shared__ unsigned sa[TR + 10][WPR];   // horizontal AND-11
    __shared__ unsigned so[TR + 10][WPR];   // horizontal OR-11

    const int b    = blockIdx.y;
    const int r0   = blockIdx.x * TR;
    const int tid  = threadIdx.x;
    const int lane = tid & 31;
    const int warp = tid >> 5;
    const int* tb  = target + (size_t)b * HW;

    // pack target -> bits: each thread builds one word from 8 independent
    // int4 loads (128B contiguous). No cross-lane dependency -> high MLP.
    for (int j = tid; j < (TR + 10) * WPR; j += 256) {
        const int lr = j >> 5, wc = j & 31;
        const int gr = r0 - 5 + lr;
        unsigned w = 0u;
        if (gr >= 0 && gr < IMH) {
            const int4* p4 = (const int4*)(tb + gr * IMW + wc * 32);
            #pragma unroll
            for (int k = 0; k < 8; k++) {
                const int4 v = p4[k];
                w |= (v.x != 0 ? 1u : 0u) << (4 * k);
                w |= (v.y != 0 ? 2u : 0u) << (4 * k);
                w |= (v.z != 0 ? 4u : 0u) << (4 * k);
                w |= (v.w != 0 ? 8u : 0u) << (4 * k);
            }
        }
        sp[lr][wc] = w;
    }
    __syncthreads();

    // horizontal 11-tap AND/OR with funnel shifts across word boundaries
    for (int j = tid; j < (TR + 10) * WPR; j += 256) {
        const int lr = j >> 5, wc = j & 31;
        const unsigned c = sp[lr][wc];
        const unsigned l = (wc > 0)        ? sp[lr][wc - 1] : 0u;
        const unsigned r = (wc < WPR - 1)  ? sp[lr][wc + 1] : 0u;
        unsigned a = c, o = c;
        #pragma unroll
        for (int k = 1; k <= 5; k++) {
            const unsigned sr = __funnelshift_r(c, r, k);  // bit i <- col i+k
            const unsigned sl = __funnelshift_l(l, c, k);  // bit i <- col i-k
            a &= (sr & sl);
            o |= (sr | sl);
        }
        sa[lr][wc] = a;
        so[lr][wc] = o;
    }
    __syncthreads();

    // vertical 11-row combine, emit packed edge + target, count edges
    unsigned ecnt = 0u;
    for (int j = tid; j < TR * WPR; j += 256) {
        const int orow = j >> 5, wc = j & 31;
        const int lr = orow + 5;
        unsigned vA = 0xffffffffu, vO = 0u;
        #pragma unroll
        for (int k = -5; k <= 5; k++) {
            vA &= sa[lr + k][wc];
            vO |= so[lr + k][wc];
        }
        const unsigned t = sp[lr][wc];
        const unsigned e = (t & ~vA) | (~t & vO);
        const int gi = (b * IMH + r0 + orow) * WPR + wc;
        g_ebits[gi] = e;
        g_tbits[gi] = t;
        ecnt += __popc(e);
    }

    // reduce edge count
    #pragma unroll
    for (int off = 16; off > 0; off >>= 1)
        ecnt += __shfl_down_sync(0xffffffffu, ecnt, off);
    __shared__ unsigned wsum[8];
    if (lane == 0) wsum[warp] = ecnt;
    __syncthreads();
    if (tid == 0) {
        unsigned s = 0u;
        #pragma unroll
        for (int i = 0; i < 8; i++) s += wsum[i];
        atomicAdd(&g_E, s);
    }
}

// ---------------- kernel 2: fused log-softmax + masked reductions ---------
__device__ __forceinline__ void proc_px(float x0, float x1, unsigned t, unsigned e,
                                        float& A, float& B) {
    const float m   = fmaxf(x0, x1);
    const float l1p = __logf(1.0f + __expf(-fabsf(x0 - x1)));
    const float lse = m + l1p;
    const float lp0 = x0 - lse;
    const float lp1 = x1 - lse;
    const float lpt = t ? lp1 : lp0;
    A += lpt;
    if (e) B += (lp0 + lp1) - 1.5f * lpt;
}

__global__ __launch_bounds__(256) void main_kernel(const float* __restrict__ s0,
                                                   const float* __restrict__ s1) {
    float A0 = 0.f, B0 = 0.f, A1 = 0.f, B1 = 0.f;
    const unsigned nch    = NPIX / 4u;                      // 4-pixel chunks
    const unsigned stride = gridDim.x * blockDim.x;
    for (unsigned c = blockIdx.x * blockDim.x + threadIdx.x; c < nch; c += stride) {
        const unsigned p   = c * 4u;
        const unsigned b   = p >> 20;          // p / HW
        const unsigned pix = p & (HW - 1u);
        const size_t base  = (size_t)b * 2u * HW + pix;

        const float4 x0 = *(const float4*)(s0 + base);
        const float4 y0 = *(const float4*)(s0 + base + HW);
        const float4 x1 = *(const float4*)(s1 + base);
        const float4 y1 = *(const float4*)(s1 + base + HW);

        const unsigned sh = p & 31u;
        const unsigned ew = g_ebits[p >> 5] >> sh;
        const unsigned tw = g_tbits[p >> 5] >> sh;

        proc_px(x0.x, y0.x,  tw       & 1u,  ew       & 1u, A0, B0);
        proc_px(x0.y, y0.y, (tw >> 1) & 1u, (ew >> 1) & 1u, A0, B0);
        proc_px(x0.z, y0.z, (tw >> 2) & 1u, (ew >> 2) & 1u, A0, B0);
        proc_px(x0.w, y0.w, (tw >> 3) & 1u, (ew >> 3) & 1u, A0, B0);

        proc_px(x1.x, y1.x,  tw       & 1u,  ew       & 1u, A1, B1);
        proc_px(x1.y, y1.y, (tw >> 1) & 1u, (ew >> 1) & 1u, A1, B1);
        proc_px(x1.z, y1.z, (tw >> 2) & 1u, (ew >> 2) & 1u, A1, B1);
        proc_px(x1.w, y1.w, (tw >> 3) & 1u, (ew >> 3) & 1u, A1, B1);
    }

    // block reduction: warp shuffle (float), cross-warp in shared, double atomics
    #pragma unroll
    for (int off = 16; off > 0; off >>= 1) {
        A0 += __shfl_down_sync(0xffffffffu, A0, off);
        B0 += __shfl_down_sync(0xffffffffu, B0, off);
        A1 += __shfl_down_sync(0xffffffffu, A1, off);
        B1 += __shfl_down_sync(0xffffffffu, B1, off);
    }
    __shared__ float red[8][4];
    const int lane = threadIdx.x & 31, warp = threadIdx.x >> 5;
    if (lane == 0) { red[warp][0] = A0; red[warp][1] = B0; red[warp][2] = A1; red[warp][3] = B1; }
    __syncthreads();
    if (threadIdx.x == 0) {
        double a0 = 0, b0 = 0, a1 = 0, b1 = 0;
        #pragma unroll
        for (int i = 0; i < 8; i++) {
            a0 += (double)red[i][0]; b0 += (double)red[i][1];
            a1 += (double)red[i][2]; b1 += (double)red[i][3];
        }
        atomicAdd(&g_acc[0], a0);
        atomicAdd(&g_acc[1], b0);
        atomicAdd(&g_acc[2], a1);
        atomicAdd(&g_acc[3], b1);
    }
}

// ---------------- kernel 3: finalize scalar --------------------------------
__global__ void fin_kernel(float* __restrict__ out) {
    const double N = (double)NPIX;
    double alpha = (double)g_E / N;
    if (alpha > 0.2) alpha = 0.2;
    const double l0 = -(g_acc[0] + alpha * g_acc[1]) / N;
    const double l1 = -(g_acc[2] + alpha * g_acc[3]) / N;
    out[0] = (float)(l0 + 0.5 * l1);
}

// ---------------- launch ---------------------------------------------------
extern "C" void kernel_launch(void* const* d_in, const int* in_sizes, int n_in,
                              void* d_out, int out_size) {
    const float* s0  = (const float*)d_in[0];
    const float* s1  = (const float*)d_in[1];
    const int*   tgt = (const int*)d_in[2];

    init_kernel<<<1, 32>>>();
    edge_kernel<<<dim3(IMH / TR, BATCH), 256>>>(tgt);
    main_kernel<<<4096, 256>>>(s0, s1);
    fin_kernel<<<1, 1>>>((float*)d_out);
}